// round 1
// baseline (speedup 1.0000x reference)
#include <cuda_runtime.h>
#include <cstdint>

#define B_ 32
#define T_ 1024
#define V_ 1000
#define L_ 128
#define S_ 258          // states 0..257 (s=0 start-star, odd=blank, even>=2 label)
#define EP_ 132         // padded emission row stride (129 used)
#define NEGF (-1e30f)
#define L2E_ 1.4426950408889634f
#define LN2_ 0.6931471805599453f

// Scratch (allocation-free rule: __device__ globals)
__device__ float g_E[(size_t)B_ * T_ * EP_];   // log2-domain emissions: [b][t][0]=blank, [b][t][1+l]=label l
__device__ float g_partial[B_];

__device__ __forceinline__ float ex2f_(float x) {
    float y; asm("ex2.approx.f32 %0, %1;" : "=f"(y) : "f"(x)); return y;
}
__device__ __forceinline__ float lg2f_(float x) {
    float y; asm("lg2.approx.f32 %0, %1;" : "=f"(y) : "f"(x)); return y;
}

// ---------------------------------------------------------------------------
// K1: per (b,t) row: log2-softmax normalizer + gather of 129 needed tokens.
// grid (T, B), 256 threads. Row = 1000 f32 = 250 float4 (4000B rows are 16B aligned).
// ---------------------------------------------------------------------------
__global__ void __launch_bounds__(256) k1_emit(const float* __restrict__ pred,
                                               const int* __restrict__ target) {
    __shared__ float row[V_];   // pred * log2(e)
    __shared__ float red[8];
    __shared__ float bc[2];
    const int t = blockIdx.x, b = blockIdx.y;
    const float* p = pred + ((size_t)b * T_ + t) * V_;
    const int tid = threadIdx.x;

    float4 v = make_float4(NEGF, NEGF, NEGF, NEGF);
    if (tid < 250) {
        v = reinterpret_cast<const float4*>(p)[tid];
        v.x *= L2E_; v.y *= L2E_; v.z *= L2E_; v.w *= L2E_;
        reinterpret_cast<float4*>(row)[tid] = v;
    }
    // block max
    float pm = fmaxf(fmaxf(v.x, v.y), fmaxf(v.z, v.w));
    #pragma unroll
    for (int o = 16; o; o >>= 1) pm = fmaxf(pm, __shfl_xor_sync(~0u, pm, o));
    if ((tid & 31) == 0) red[tid >> 5] = pm;
    __syncthreads();
    if (tid < 32) {
        float m = (tid < 8) ? red[tid] : NEGF;
        #pragma unroll
        for (int o = 4; o; o >>= 1) m = fmaxf(m, __shfl_xor_sync(~0u, m, o));
        if (tid == 0) bc[0] = m;
    }
    __syncthreads();
    const float mx = bc[0];
    // block sum of 2^(y-mx)
    float ps = 0.f;
    if (tid < 250)
        ps = ex2f_(v.x - mx) + ex2f_(v.y - mx) + ex2f_(v.z - mx) + ex2f_(v.w - mx);
    #pragma unroll
    for (int o = 16; o; o >>= 1) ps += __shfl_xor_sync(~0u, ps, o);
    if ((tid & 31) == 0) red[tid >> 5] = ps;
    __syncthreads();
    if (tid < 32) {
        float s = (tid < 8) ? red[tid] : 0.f;
        #pragma unroll
        for (int o = 4; o; o >>= 1) s += __shfl_xor_sync(~0u, s, o);
        if (tid == 0) bc[1] = mx + lg2f_(s);
    }
    __syncthreads();
    const float lse2 = bc[1];
    if (tid < L_ + 1) {
        const int tok = (tid == 0) ? 0 : target[b * L_ + tid - 1];
        g_E[((size_t)b * T_ + t) * EP_ + tid] = row[tok] - lse2;
    }
}

// ---------------------------------------------------------------------------
// K2: W-CTC forward DP, log2 domain. One block per batch, 288 threads:
// tid 0..257 -> state s=tid, tid 258 -> end-star, rest idle.
// Double-buffered alpha in smem, ONE barrier per step; own alpha kept in reg;
// emissions prefetched 2 timesteps ahead.
// ---------------------------------------------------------------------------
__global__ void __launch_bounds__(288) k2_dp(const int* __restrict__ target,
                                             const int* __restrict__ tlen) {
    __shared__ float bufA[S_], bufB[S_];
    __shared__ int tgt[L_];
    const int b = blockIdx.x;
    const int tid = threadIdx.x;
    if (tid < L_) tgt[tid] = target[b * L_ + tid];
    const int tl = tlen[b];
    const int ll = 2 * tl, lb = ll + 1;
    __syncthreads();

    const int s = tid;
    const bool active = (s < S_);
    const bool isStar = (s == 0);
    const bool isBlank = (s & 1) != 0;
    int eidx = 0;
    bool skip = false, valid = false;
    if (active) {
        valid = (s <= 2 * tl + 1);
        if (!isStar && !isBlank) {              // label state
            const int lab = (s - 2) >> 1;
            eidx = lab + 1;
            skip = (s == 2) || (tgt[lab] != tgt[lab - 1]);
        }
    }
    const float* ep = g_E + (size_t)b * T_ * EP_ + eidx;

    // init at t=0
    float a = NEGF;
    if (active) {
        const float e0 = isStar ? 0.f : ep[0];
        if (s == 0) a = 0.f;
        else if (s == 1 || s == 2) a = e0;
        if (!valid) a = NEGF;
        bufA[s] = a;
    }
    float es = NEGF;
    // prefetch emissions for t=1, t=2
    float e1 = 0.f, e2p = 0.f;
    if (active && !isStar) { e1 = ep[(size_t)1 * EP_]; e2p = ep[(size_t)2 * EP_]; }
    __syncthreads();

    float* cur = bufA;
    float* nxt = bufB;
    for (int t = 1; t < T_; t++) {
        const float e = e1;
        e1 = e2p;
        if (active && !isStar && (t + 2) < T_) e2p = ep[(size_t)(t + 2) * EP_];

        if (tid == S_) {   // end-star absorbs from old alpha
            const float x = cur[ll], y = cur[lb];
            const float m = fmaxf(es, fmaxf(x, y));
            es = m + lg2f_(ex2f_(es - m) + ex2f_(x - m) + ex2f_(y - m));
        }
        if (active) {
            const float a0 = a;                                   // cur[s] (own reg)
            const float a1 = (s >= 1) ? cur[s - 1] : NEGF;
            const float a2 = skip ? cur[s - 2] : NEGF;
            const float m = fmaxf(a0, fmaxf(a1, a2));
            const float r = m + lg2f_(ex2f_(a0 - m) + ex2f_(a1 - m) + ex2f_(a2 - m));
            a = valid ? ((isStar ? 0.f : e) + r) : NEGF;
            nxt[s] = a;
        }
        __syncthreads();   // orders this step's cur-reads vs next step's writes into cur
        float* tmp = cur; cur = nxt; nxt = tmp;
    }

    if (tid == S_) {
        const float x = cur[ll], y = cur[lb];
        const float m = fmaxf(es, fmaxf(x, y));
        const float tot2 = m + lg2f_(ex2f_(es - m) + ex2f_(x - m) + ex2f_(y - m));
        const float nll = -tot2 * LN2_;
        g_partial[b] = nll / (float)tl;
    }
}

// ---------------------------------------------------------------------------
// K3: mean over batches -> scalar output
// ---------------------------------------------------------------------------
__global__ void k3_final(float* __restrict__ out) {
    float v = (threadIdx.x < B_) ? g_partial[threadIdx.x] : 0.f;
    #pragma unroll
    for (int o = 16; o; o >>= 1) v += __shfl_xor_sync(~0u, v, o);
    if (threadIdx.x == 0) out[0] = v / (float)B_;
}

extern "C" void kernel_launch(void* const* d_in, const int* in_sizes, int n_in,
                              void* d_out, int out_size) {
    const float* pred   = (const float*)d_in[0];   // (B,T,V) f32
    const int*   target = (const int*)d_in[1];     // (B,L) i32
    const int*   tlen   = (const int*)d_in[2];     // (B,) i32
    (void)in_sizes; (void)n_in; (void)out_size;

    dim3 g1(T_, B_);
    k1_emit<<<g1, 256>>>(pred, target);
    k2_dp<<<B_, 288>>>(target, tlen);
    k3_final<<<1, 32>>>((float*)d_out);
}

// round 2
// speedup vs baseline: 1.1570x; 1.1570x over previous
#include <cuda_runtime.h>
#include <cstdint>

#define B_ 32
#define T_ 1024
#define V_ 1000
#define L_ 128
#define R_ 129            // emission rows: 0 = blank, 1+k = label k
#define NEGF (-1e30f)
#define L2E_ 1.4426950408889634f
#define LN2_ 0.6931471805599453f

// scratch (allocation-free rule: __device__ globals)
__device__ float g_Et[(size_t)B_ * R_ * T_];   // log2-domain emissions, transposed: [b][row][t]
__device__ float g_partial[B_];

__device__ __forceinline__ float ex2f_(float x){ float y; asm("ex2.approx.f32 %0,%1;":"=f"(y):"f"(x)); return y; }
__device__ __forceinline__ float lg2f_(float x){ float y; asm("lg2.approx.f32 %0,%1;":"=f"(y):"f"(x)); return y; }

// 2-MUFU logsumexp2 (log2 domain)
__device__ __forceinline__ float lse2_(float x, float y){
    float m = fmaxf(x, y);
    float d = fminf(x, y) - m;                 // <= 0
    return m + lg2f_(1.0f + ex2f_(d));
}
// 4-MUFU logsumexp3 (log2 domain)
__device__ __forceinline__ float lse3_(float a, float b, float c){
    float m = fmaxf(a, fmaxf(b, c));
    return m + lg2f_(ex2f_(a - m) + ex2f_(b - m) + ex2f_(c - m));
}

// ---------------------------------------------------------------------------
// K1: warp per (b,t) row. Row kept in 8 float4 regs; shfl-only reductions;
// gather of 129 tokens hits L1; writes transposed emission table.
// ---------------------------------------------------------------------------
__global__ void __launch_bounds__(256) k1_emit(const float* __restrict__ pred,
                                               const int* __restrict__ target){
    const int w    = blockIdx.x * 8 + (threadIdx.x >> 5);   // flat row = b*T + t
    const int lane = threadIdx.x & 31;
    const int b    = w >> 10;
    const int t    = w & (T_ - 1);
    const float* p = pred + (size_t)w * V_;

    float4 v[8];
    float m = NEGF;
    #pragma unroll
    for (int k = 0; k < 8; k++){
        const int i4 = lane + 32 * k;
        if (i4 < 250){
            v[k] = reinterpret_cast<const float4*>(p)[i4];
            m = fmaxf(m, fmaxf(fmaxf(v[k].x, v[k].y), fmaxf(v[k].z, v[k].w)));
        } else {
            v[k] = make_float4(NEGF, NEGF, NEGF, NEGF);
        }
    }
    #pragma unroll
    for (int o = 16; o; o >>= 1) m = fmaxf(m, __shfl_xor_sync(~0u, m, o));

    float s = 0.f;
    #pragma unroll
    for (int k = 0; k < 8; k++){
        s += ex2f_((v[k].x - m) * L2E_) + ex2f_((v[k].y - m) * L2E_)
           + ex2f_((v[k].z - m) * L2E_) + ex2f_((v[k].w - m) * L2E_);
    }
    #pragma unroll
    for (int o = 16; o; o >>= 1) s += __shfl_xor_sync(~0u, s, o);
    const float lg2s = lg2f_(s);

    const int* tg = target + b * L_;
    #pragma unroll
    for (int r = lane; r < R_; r += 32){
        const int tok = r ? tg[r - 1] : 0;
        g_Et[((size_t)(b * R_ + r) << 10) + t] = (p[tok] - m) * L2E_ - lg2s;
    }
}

// ---------------------------------------------------------------------------
// K2: W-CTC forward DP, ONE warp per batch, fully warp-synchronous.
// State pairing: pair k: b_k = alpha[2k+1] (blank), l_k = alpha[2k+2] (label).
// Lane i owns pairs 4i..4i+3; lane 31 also owns final blank s=257 (bF).
// Star state alpha[0] == 0 forever (self-loop only, emission 0) -> constant.
// End-star: total = lse over t of lse(alpha_t[ll], alpha_t[lb]) -> owning
// lanes just store 2 floats/step to a smem ring; reduced once at the end.
// ---------------------------------------------------------------------------
__global__ void __launch_bounds__(32) k2_dp(const int* __restrict__ target,
                                            const int* __restrict__ tlen){
    __shared__ float sll[T_], slb[T_];
    const int b    = blockIdx.x;
    const int lane = threadIdx.x;
    const int tl   = tlen[b];                  // in [64,128]
    const int* tg  = target + b * L_;

    bool skip[4], vb[4], vl[4];
    const float* __restrict__ ebp = g_Et + (size_t)b * R_ * T_;   // blank row (r=0)
    const float* rowp[4];
    #pragma unroll
    for (int j = 0; j < 4; j++){
        const int k = 4 * lane + j;
        skip[j] = (k == 0) || (tg[k] != tg[k - 1]);
        vb[j]   = (k <= tl);                   // blank s=2k+1 valid
        vl[j]   = (k <  tl);                   // label s=2k+2 valid
        rowp[j] = ebp + (size_t)(1 + k) * T_;
    }
    const bool vbF     = (tl == 128) && (lane == 31);   // s=257 valid only at tl=128
    const int  lane_ll = (tl - 1) >> 2, j_ll = (tl - 1) & 3;   // ll -> l_{tl-1}
    const bool lb_pair = (tl < 128);
    const int  lane_lb = tl >> 2,       j_lb = tl & 3;          // lb -> b_{tl} (or bF)

    // emission double buffers (float4 = 4 timesteps)
    float4 cEb, cE0, cE1, cE2, cE3, nEb, nE0, nE1, nE2, nE3;
    cEb = reinterpret_cast<const float4*>(ebp)[0];
    cE0 = reinterpret_cast<const float4*>(rowp[0])[0];
    cE1 = reinterpret_cast<const float4*>(rowp[1])[0];
    cE2 = reinterpret_cast<const float4*>(rowp[2])[0];
    cE3 = reinterpret_cast<const float4*>(rowp[3])[0];

    float bq[4], lq[4], bF = NEGF;
    #pragma unroll
    for (int j = 0; j < 4; j++){ bq[j] = NEGF; lq[j] = NEGF; }
    // t=0 init: alpha0[1] = blank emission, alpha0[2] = label-0 emission (tl>=64 -> valid)
    if (lane == 0){ bq[0] = cEb.x; lq[0] = cE0.x; }

    auto store_acc = [&](int t){
        const float vll = (j_ll == 0) ? lq[0] : (j_ll == 1) ? lq[1] : (j_ll == 2) ? lq[2] : lq[3];
        if (lane == lane_ll) sll[t] = vll;
        if (lb_pair){
            const float vlb = (j_lb == 0) ? bq[0] : (j_lb == 1) ? bq[1] : (j_lb == 2) ? bq[2] : bq[3];
            if (lane == lane_lb) slb[t] = vlb;
        } else {
            if (lane == 31) slb[t] = bF;
        }
    };

    auto step = [&](float eb, float e0, float e1, float e2, float e3, int t){
        float lm1 = __shfl_up_sync(0xffffffffu, lq[3], 1);
        if (lane == 0) lm1 = 0.0f;             // star value
        const float lp0 = lm1, lp1 = lq[0], lp2 = lq[1], lp3 = lq[2];
        // blanks: b_k' = Eb + lse2(b_k, l_{k-1})
        const float nb0 = eb + lse2_(bq[0], lp0);
        const float nb1 = eb + lse2_(bq[1], lp1);
        const float nb2 = eb + lse2_(bq[2], lp2);
        const float nb3 = eb + lse2_(bq[3], lp3);
        // labels: l_k' = E_k + lse3(l_k, b_k, skip ? l_{k-1} : -inf)
        const float nl0 = e0 + lse3_(lq[0], bq[0], skip[0] ? lp0 : NEGF);
        const float nl1 = e1 + lse3_(lq[1], bq[1], skip[1] ? lp1 : NEGF);
        const float nl2 = e2 + lse3_(lq[2], bq[2], skip[2] ? lp2 : NEGF);
        const float nl3 = e3 + lse3_(lq[3], bq[3], skip[3] ? lp3 : NEGF);
        // final blank s=257: from itself and l_127 (lane 31's lq[3])
        const float nbF = eb + lse2_(bF, lq[3]);
        bq[0] = vb[0] ? nb0 : NEGF;  lq[0] = vl[0] ? nl0 : NEGF;
        bq[1] = vb[1] ? nb1 : NEGF;  lq[1] = vl[1] ? nl1 : NEGF;
        bq[2] = vb[2] ? nb2 : NEGF;  lq[2] = vl[2] ? nl2 : NEGF;
        bq[3] = vb[3] ? nb3 : NEGF;  lq[3] = vl[3] ? nl3 : NEGF;
        bF = vbF ? nbF : NEGF;
        store_acc(t);
    };

    store_acc(0);
    // prefetch group 1, run steps t=1..3 from group 0
    nEb = reinterpret_cast<const float4*>(ebp)[1];
    nE0 = reinterpret_cast<const float4*>(rowp[0])[1];
    nE1 = reinterpret_cast<const float4*>(rowp[1])[1];
    nE2 = reinterpret_cast<const float4*>(rowp[2])[1];
    nE3 = reinterpret_cast<const float4*>(rowp[3])[1];
    step(cEb.y, cE0.y, cE1.y, cE2.y, cE3.y, 1);
    step(cEb.z, cE0.z, cE1.z, cE2.z, cE3.z, 2);
    step(cEb.w, cE0.w, cE1.w, cE2.w, cE3.w, 3);

    for (int g = 1; g < 256; g++){
        cEb = nEb; cE0 = nE0; cE1 = nE1; cE2 = nE2; cE3 = nE3;
        if (g < 255){
            nEb = reinterpret_cast<const float4*>(ebp)[g + 1];
            nE0 = reinterpret_cast<const float4*>(rowp[0])[g + 1];
            nE1 = reinterpret_cast<const float4*>(rowp[1])[g + 1];
            nE2 = reinterpret_cast<const float4*>(rowp[2])[g + 1];
            nE3 = reinterpret_cast<const float4*>(rowp[3])[g + 1];
        }
        const int t0 = 4 * g;
        step(cEb.x, cE0.x, cE1.x, cE2.x, cE3.x, t0);
        step(cEb.y, cE0.y, cE1.y, cE2.y, cE3.y, t0 + 1);
        step(cEb.z, cE0.z, cE1.z, cE2.z, cE3.z, t0 + 2);
        step(cEb.w, cE0.w, cE1.w, cE2.w, cE3.w, t0 + 3);
    }

    // final reduction: total = lse over 2048 stored values
    __syncwarp();
    float m = NEGF;
    for (int i = lane; i < T_; i += 32) m = fmaxf(m, fmaxf(sll[i], slb[i]));
    #pragma unroll
    for (int o = 16; o; o >>= 1) m = fmaxf(m, __shfl_xor_sync(~0u, m, o));
    float s = 0.f;
    for (int i = lane; i < T_; i += 32) s += ex2f_(sll[i] - m) + ex2f_(slb[i] - m);
    #pragma unroll
    for (int o = 16; o; o >>= 1) s += __shfl_xor_sync(~0u, s, o);
    if (lane == 0){
        const float tot2 = m + lg2f_(s);       // log2 total likelihood
        g_partial[b] = (-tot2 * LN2_) / (float)tl;
    }
}

// ---------------------------------------------------------------------------
// K3: mean over batches -> scalar
// ---------------------------------------------------------------------------
__global__ void k3_final(float* __restrict__ out){
    float v = (threadIdx.x < B_) ? g_partial[threadIdx.x] : 0.f;
    #pragma unroll
    for (int o = 16; o; o >>= 1) v += __shfl_xor_sync(~0u, v, o);
    if (threadIdx.x == 0) out[0] = v / (float)B_;
}

extern "C" void kernel_launch(void* const* d_in, const int* in_sizes, int n_in,
                              void* d_out, int out_size) {
    const float* pred   = (const float*)d_in[0];   // (B,T,V) f32
    const int*   target = (const int*)d_in[1];     // (B,L) i32
    const int*   tlen   = (const int*)d_in[2];     // (B,) i32
    (void)in_sizes; (void)n_in; (void)out_size;

    k1_emit<<<B_ * T_ / 8, 256>>>(pred, target);
    k2_dp<<<B_, 32>>>(target, tlen);
    k3_final<<<1, 32>>>((float*)d_out);
}

// round 3
// speedup vs baseline: 2.1240x; 1.8357x over previous
#include <cuda_runtime.h>
#include <cstdint>

#define B_ 32
#define T_ 1024
#define V_ 1000
#define L_ 128
#define NG_ 256           // time groups of 4 steps
#define SLOTS_ 129        // slots 0..127 = labels (slot = j*32+lane, pair k=4*lane+j), 128 = blank
#define NEGF (-1e30f)
#define L2E_ 1.4426950408889634f
#define LN2_ 0.6931471805599453f

// scratch (allocation-free rule: __device__ globals)
// emissions, DP-native layout: [b][g][slot][4 timesteps], log2 domain
__device__ float g_E2[(size_t)B_ * NG_ * SLOTS_ * 4];
__device__ float g_partial[B_];

__device__ __forceinline__ float ex2f_(float x){ float y; asm("ex2.approx.f32 %0,%1;":"=f"(y):"f"(x)); return y; }
__device__ __forceinline__ float lg2f_(float x){ float y; asm("lg2.approx.f32 %0,%1;":"=f"(y):"f"(x)); return y; }

__device__ __forceinline__ float lse2_(float x, float y){
    float m = fmaxf(x, y);
    float d = fminf(x, y) - m;                 // <= 0
    return m + lg2f_(1.0f + ex2f_(d));
}

// ---------------------------------------------------------------------------
// K1: warp per (b,t) row: log2-softmax + gather of 129 tokens, staged through
// smem, written out as fully-coalesced [b][g][slot][4] chunks (2 groups/block).
// Invalid-label rows (k >= tlen[b]) are poisoned to NEGF here, so K2 needs no
// per-step masking at all.
// ---------------------------------------------------------------------------
__global__ void __launch_bounds__(256) k1_emit(const float* __restrict__ pred,
                                               const int* __restrict__ target,
                                               const int* __restrict__ tlen){
    __shared__ float sE[SLOTS_ * 12];          // [slot][tloc(8) pad->12]
    const int wid  = threadIdx.x >> 5;
    const int lane = threadIdx.x & 31;
    const int w    = blockIdx.x * 8 + wid;     // flat row = b*T + t
    const int b    = w >> 10;
    const int t    = w & (T_ - 1);
    const int tloc = t & 7;
    const int g0   = (t & ~7) >> 2;            // first of the block's 2 groups
    const float* p = pred + (size_t)w * V_;
    const int tl   = tlen[b];

    float4 v[8];
    float m = NEGF;
    #pragma unroll
    for (int k = 0; k < 8; k++){
        const int i4 = lane + 32 * k;
        if (i4 < 250){
            v[k] = reinterpret_cast<const float4*>(p)[i4];
            m = fmaxf(m, fmaxf(fmaxf(v[k].x, v[k].y), fmaxf(v[k].z, v[k].w)));
        } else {
            v[k] = make_float4(NEGF, NEGF, NEGF, NEGF);
        }
    }
    #pragma unroll
    for (int o = 16; o; o >>= 1) m = fmaxf(m, __shfl_xor_sync(~0u, m, o));

    float s = 0.f;
    #pragma unroll
    for (int k = 0; k < 8; k++){
        s += ex2f_((v[k].x - m) * L2E_) + ex2f_((v[k].y - m) * L2E_)
           + ex2f_((v[k].z - m) * L2E_) + ex2f_((v[k].w - m) * L2E_);
    }
    #pragma unroll
    for (int o = 16; o; o >>= 1) s += __shfl_xor_sync(~0u, s, o);
    const float lg2s = lg2f_(s);

    const int* tg = target + b * L_;
    #pragma unroll
    for (int r = lane; r < SLOTS_; r += 32){
        int slot; float val;
        if (r == 0){
            slot = 128;                                     // blank (token 0)
            val  = (p[0] - m) * L2E_ - lg2s;
        } else {
            const int k = r - 1;
            slot = ((k & 3) << 5) + (k >> 2);               // j*32 + owner-lane
            val  = (k < tl) ? ((p[tg[k]] - m) * L2E_ - lg2s) : NEGF;
        }
        sE[slot * 12 + tloc] = val;
    }
    __syncthreads();
    // write 2 groups x 129 float4, fully coalesced
    for (int k = threadIdx.x; k < 2 * SLOTS_; k += 256){
        const int gg = (k >= SLOTS_) ? 1 : 0;
        const int sl = k - gg * SLOTS_;
        const float4 o = *reinterpret_cast<const float4*>(&sE[sl * 12 + gg * 4]);
        reinterpret_cast<float4*>(g_E2)[((size_t)b * NG_ + g0 + gg) * SLOTS_ + sl] = o;
    }
}

// ---------------------------------------------------------------------------
// K2: W-CTC forward DP, one warp per batch, warp-synchronous, all 258 states
// in registers. Fused shared-max update: per pair, 3 ex2 + 2 lg2 give both the
// blank and label recurrences. No per-step masking (emissions pre-poisoned).
// End-star deferred: alpha_t[ll], alpha_t[lb] ring-buffered to smem, one lse
// reduction at the end.
// ---------------------------------------------------------------------------
__global__ void __launch_bounds__(32) k2_dp(const int* __restrict__ target,
                                            const int* __restrict__ tlen){
    __shared__ float sll[T_], slb[T_];
    const int b    = blockIdx.x;
    const int lane = threadIdx.x;
    const int tl   = tlen[b];
    const int* tg  = target + b * L_;

    float sk[4];
    #pragma unroll
    for (int j = 0; j < 4; j++){
        const int k = 4 * lane + j;
        sk[j] = (k == 0 || tg[k] != tg[k - 1]) ? 1.0f : 0.0f;
    }

    const float4* chunk = reinterpret_cast<const float4*>(g_E2) + (size_t)b * NG_ * SLOTS_;

    const int  lane_ll = (tl - 1) >> 2, j_ll = (tl - 1) & 3;  // ll -> label tl-1
    const bool lbp     = (tl < 128);
    const int  lane_lb = lbp ? (tl >> 2) : 31;
    const int  j_lb    = lbp ? (tl & 3) : -1;                  // -1 -> final blank bF
    const bool wll = (lane == lane_ll);
    const bool wlb = (lane == lane_lb);

    float4 cb, c0, c1, c2, c3, nb4, n0, n1, n2, n3;
    #define LOADG(B_V,V0,V1,V2,V3,g) do{ const float4* c_ = chunk + (size_t)(g) * SLOTS_; \
        B_V = c_[128]; V0 = c_[lane]; V1 = c_[32 + lane]; V2 = c_[64 + lane]; V3 = c_[96 + lane]; }while(0)

    LOADG(cb, c0, c1, c2, c3, 0);

    float bq[4], lq[4], bF = NEGF;
    #pragma unroll
    for (int j = 0; j < 4; j++){ bq[j] = NEGF; lq[j] = NEGF; }
    if (lane == 0){ bq[0] = cb.x; lq[0] = c0.x; }             // alpha0[1], alpha0[2]
    float lp = (lane == 0) ? 0.0f : NEGF;                     // l_{4*lane-1} boundary (star for lane 0)

    auto store_acc = [&](int t){
        if (wll){
            float v = lq[0];
            if (j_ll == 1) v = lq[1];
            if (j_ll == 2) v = lq[2];
            if (j_ll == 3) v = lq[3];
            sll[t] = v;
        }
        if (wlb){
            float v = bF;
            if (j_lb == 0) v = bq[0];
            if (j_lb == 1) v = bq[1];
            if (j_lb == 2) v = bq[2];
            if (j_lb == 3) v = bq[3];
            slb[t] = v;
        }
    };

    auto step = [&](float eb, float e0, float e1, float e2, float e3, int t){
        const float el[4] = {e0, e1, e2, e3};
        const float lpv[4] = {lp, lq[0], lq[1], lq[2]};
        float nbv[4], nlv[4];
        #pragma unroll
        for (int j = 0; j < 4; j++){
            const float m = fmaxf(fmaxf(lq[j], bq[j]), lpv[j]);
            const float u = ex2f_(bq[j]  - m);
            const float vv= ex2f_(lpv[j] - m);
            const float w = ex2f_(lq[j]  - m);
            nbv[j] = eb    + m + lg2f_(u + vv);
            nlv[j] = el[j] + m + lg2f_(fmaf(vv, sk[j], w + u));
        }
        const float nbF = eb + lse2_(bF, lq[3]);              // final blank s=257
        #pragma unroll
        for (int j = 0; j < 4; j++){ bq[j] = nbv[j]; lq[j] = nlv[j]; }
        bF = nbF;
        lp = __shfl_up_sync(0xffffffffu, lq[3], 1);           // boundary for next step
        if (lane == 0) lp = 0.0f;                             // star stays 0
        store_acc(t);
    };

    store_acc(0);
    LOADG(nb4, n0, n1, n2, n3, 1);
    step(cb.y, c0.y, c1.y, c2.y, c3.y, 1);
    step(cb.z, c0.z, c1.z, c2.z, c3.z, 2);
    step(cb.w, c0.w, c1.w, c2.w, c3.w, 3);

    for (int g = 1; g < NG_; g++){
        cb = nb4; c0 = n0; c1 = n1; c2 = n2; c3 = n3;
        if (g < NG_ - 1) LOADG(nb4, n0, n1, n2, n3, g + 1);
        const int t0 = 4 * g;
        step(cb.x, c0.x, c1.x, c2.x, c3.x, t0);
        step(cb.y, c0.y, c1.y, c2.y, c3.y, t0 + 1);
        step(cb.z, c0.z, c1.z, c2.z, c3.z, t0 + 2);
        step(cb.w, c0.w, c1.w, c2.w, c3.w, t0 + 3);
    }
    #undef LOADG

    __syncwarp();
    float m = NEGF;
    for (int i = lane; i < T_; i += 32) m = fmaxf(m, fmaxf(sll[i], slb[i]));
    #pragma unroll
    for (int o = 16; o; o >>= 1) m = fmaxf(m, __shfl_xor_sync(~0u, m, o));
    float s = 0.f;
    for (int i = lane; i < T_; i += 32) s += ex2f_(sll[i] - m) + ex2f_(slb[i] - m);
    #pragma unroll
    for (int o = 16; o; o >>= 1) s += __shfl_xor_sync(~0u, s, o);
    if (lane == 0){
        const float tot2 = m + lg2f_(s);                      // log2 likelihood
        g_partial[b] = (-tot2 * LN2_) / (float)tl;
    }
}

// ---------------------------------------------------------------------------
// K3: mean over batches -> scalar
// ---------------------------------------------------------------------------
__global__ void k3_final(float* __restrict__ out){
    float v = (threadIdx.x < B_) ? g_partial[threadIdx.x] : 0.f;
    #pragma unroll
    for (int o = 16; o; o >>= 1) v += __shfl_xor_sync(~0u, v, o);
    if (threadIdx.x == 0) out[0] = v / (float)B_;
}

extern "C" void kernel_launch(void* const* d_in, const int* in_sizes, int n_in,
                              void* d_out, int out_size) {
    const float* pred   = (const float*)d_in[0];   // (B,T,V) f32
    const int*   target = (const int*)d_in[1];     // (B,L) i32
    const int*   tlen   = (const int*)d_in[2];     // (B,) i32
    (void)in_sizes; (void)n_in; (void)out_size;

    k1_emit<<<B_ * T_ / 8, 256>>>(pred, target, tlen);
    k2_dp<<<B_, 32>>>(target, tlen);
    k3_final<<<1, 32>>>((float*)d_out);
}